// round 8
// baseline (speedup 1.0000x reference)
#include <cuda_runtime.h>
#include <cuda_bf16.h>
#include <stdint.h>
#include <math.h>

#define N_TOK 8192
#define C_DIM 1024
#define H_DIM 4096
#define E_NUM 5
#define PADDED_CAP (N_TOK + E_NUM * 128)   // 8832

// ---------------------------------------------------------------------------
// Device scratch (allocation-free per harness rules)
// ---------------------------------------------------------------------------
__device__ float g_scale[N_TOK];
__device__ int   g_sorted[N_TOK];
__device__ int   g_count[E_NUM];
__device__ int   g_offset[E_NUM + 1];
__device__ int   g_poff[E_NUM + 1];
__device__ int   g_cursor[E_NUM];

// bf16 hi/lo planes
__device__ __align__(16) __nv_bfloat16 g_h_hi[(size_t)N_TOK * C_DIM];
__device__ __align__(16) __nv_bfloat16 g_h_lo[(size_t)N_TOK * C_DIM];
__device__ __align__(16) __nv_bfloat16 g_act_hi[(size_t)PADDED_CAP * H_DIM];
__device__ __align__(16) __nv_bfloat16 g_act_lo[(size_t)PADDED_CAP * H_DIM];

// k-pair-packed weight planes: [E][K/2][N] uint32, elem = bf16x2(k, k+1)
__device__ __align__(16) uint32_t g_w1p_hi[(size_t)E_NUM * (C_DIM / 2) * H_DIM];
__device__ __align__(16) uint32_t g_w1p_lo[(size_t)E_NUM * (C_DIM / 2) * H_DIM];
__device__ __align__(16) uint32_t g_w2p_hi[(size_t)E_NUM * (H_DIM / 2) * C_DIM];
__device__ __align__(16) uint32_t g_w2p_lo[(size_t)E_NUM * (H_DIM / 2) * C_DIM];

// ---------------------------------------------------------------------------
// PTX helpers
// ---------------------------------------------------------------------------
__device__ __forceinline__ uint32_t smem_u32(const void* p) {
    uint32_t a;
    asm("{ .reg .u64 t; cvta.to.shared.u64 t, %1; cvt.u32.u64 %0, t; }" : "=r"(a) : "l"(p));
    return a;
}
__device__ __forceinline__ uint32_t lds32(uint32_t a) {
    uint32_t v;
    asm volatile("ld.shared.b32 %0, [%1];" : "=r"(v) : "r"(a));
    return v;
}
__device__ __forceinline__ void cp16(uint32_t dst, const void* src) {
    asm volatile("cp.async.cg.shared.global [%0], [%1], 16;" :: "r"(dst), "l"(src));
}
__device__ __forceinline__ void cp16s(uint32_t dst, const void* src, uint32_t sz) {
    asm volatile("cp.async.cg.shared.global [%0], [%1], 16, %2;" :: "r"(dst), "l"(src), "r"(sz));
}
__device__ __forceinline__ void cp_commit() {
    asm volatile("cp.async.commit_group;" ::: "memory");
}
__device__ __forceinline__ void cp_wait1() {
    asm volatile("cp.async.wait_group 1;" ::: "memory");
}
__device__ __forceinline__ void cp_wait0() {
    asm volatile("cp.async.wait_group 0;" ::: "memory");
}
__device__ __forceinline__ void mma16816(float* c, const uint32_t* a, uint32_t b0, uint32_t b1) {
    asm volatile("mma.sync.aligned.m16n8k16.row.col.f32.bf16.bf16.f32 "
                 "{%0,%1,%2,%3}, {%4,%5,%6,%7}, {%8,%9}, {%0,%1,%2,%3};"
                 : "+f"(c[0]), "+f"(c[1]), "+f"(c[2]), "+f"(c[3])
                 : "r"(a[0]), "r"(a[1]), "r"(a[2]), "r"(a[3]), "r"(b0), "r"(b1));
}
__device__ __forceinline__ uint32_t pack_hi(float x, float y) {
    __nv_bfloat162 p; p.x = __float2bfloat16(x); p.y = __float2bfloat16(y);
    return *reinterpret_cast<uint32_t*>(&p);
}
__device__ __forceinline__ uint32_t pack_lo(float x, float y) {
    __nv_bfloat16 hx = __float2bfloat16(x), hy = __float2bfloat16(y);
    __nv_bfloat162 p;
    p.x = __float2bfloat16(x - __bfloat162float(hx));
    p.y = __float2bfloat16(y - __bfloat162float(hy));
    return *reinterpret_cast<uint32_t*>(&p);
}

// ---------------------------------------------------------------------------
// Small pipeline kernels
// ---------------------------------------------------------------------------
__global__ void init_kernel() {
    if (threadIdx.x < E_NUM) { g_count[threadIdx.x] = 0; g_cursor[threadIdx.x] = 0; }
}

__global__ void __launch_bounds__(256) ln_conf_kernel(
    const float* __restrict__ x, const int* __restrict__ winners,
    const float* __restrict__ gamma, const float* __restrict__ beta,
    const float* __restrict__ wc, const float* __restrict__ bc)
{
    int n = blockIdx.x, tid = threadIdx.x;
    const float* xr = x + (size_t)n * C_DIM;
    float xv[4], s = 0.f, s2 = 0.f;
#pragma unroll
    for (int i = 0; i < 4; i++) { float v = xr[tid + 256 * i]; xv[i] = v; s += v; s2 += v * v; }
#pragma unroll
    for (int off = 16; off > 0; off >>= 1) {
        s  += __shfl_down_sync(0xffffffffu, s,  off);
        s2 += __shfl_down_sync(0xffffffffu, s2, off);
    }
    __shared__ float sh1[8], sh2[8];
    __shared__ float s_mean, s_rstd;
    int warp = tid >> 5, lane = tid & 31;
    if (lane == 0) { sh1[warp] = s; sh2[warp] = s2; }
    __syncthreads();
    if (tid == 0) {
        float ts = 0.f, ts2 = 0.f;
#pragma unroll
        for (int w = 0; w < 8; w++) { ts += sh1[w]; ts2 += sh2[w]; }
        float mean = ts * (1.f / C_DIM);
        float var = ts2 * (1.f / C_DIM) - mean * mean;
        s_mean = mean; s_rstd = rsqrtf(var + 1e-5f);
    }
    __syncthreads();
    float mean = s_mean, rstd = s_rstd;
    int win = winners[n];
    const float* wcr = wc + (size_t)win * C_DIM;
    float dot = 0.f;
#pragma unroll
    for (int i = 0; i < 4; i++) {
        int c = tid + 256 * i;
        float hv = (xv[i] - mean) * rstd * gamma[c] + beta[c];
        __nv_bfloat16 hh = __float2bfloat16(hv);
        g_h_hi[(size_t)n * C_DIM + c] = hh;
        g_h_lo[(size_t)n * C_DIM + c] = __float2bfloat16(hv - __bfloat162float(hh));
        dot += hv * wcr[c];
    }
#pragma unroll
    for (int off = 16; off > 0; off >>= 1) dot += __shfl_down_sync(0xffffffffu, dot, off);
    if (lane == 0) sh1[warp] = dot;
    __syncthreads();
    if (tid == 0) {
        float t = 0.f;
#pragma unroll
        for (int w = 0; w < 8; w++) t += sh1[w];
        t += bc[win];
        float conf = 1.f / (1.f + expf(-t));
        g_scale[n] = conf / (conf + 1e-6f);
        atomicAdd(&g_count[win], 1);
    }
}

__global__ void scan_kernel() {
    if (threadIdx.x == 0) {
        int acc = 0, pacc = 0;
        g_offset[0] = 0; g_poff[0] = 0;
        for (int e = 0; e < E_NUM; e++) {
            int c = g_count[e];
            acc += c;
            g_offset[e + 1] = acc;
            g_cursor[e] = g_offset[e];
            pacc += ((c + 127) / 128) * 128;
            g_poff[e + 1] = pacc;
        }
    }
}

__global__ void scatter_kernel(const int* __restrict__ winners) {
    int n = blockIdx.x * blockDim.x + threadIdx.x;
    if (n < N_TOK) {
        int e = winners[n];
        int pos = atomicAdd(&g_cursor[e], 1);
        g_sorted[pos] = n;
    }
}

// ---------------------------------------------------------------------------
// weight convert: w [E][K][N] fp32 -> planes [E][K/2][N] uint32 (bf16x2 of k,k+1)
// fully coalesced, elementwise (no transpose).
// ---------------------------------------------------------------------------
template<int LOGN>
__global__ void __launch_bounds__(256) conv_w(
    const float* __restrict__ w, uint32_t* __restrict__ phi, uint32_t* __restrict__ plo, int Krows)
{
    constexpr int N = 1 << LOGN;
    size_t half = (size_t)(Krows / 2) << LOGN;
    size_t eW = (size_t)blockIdx.z * Krows << LOGN;
    size_t eP = (size_t)blockIdx.z * half;
    size_t i = (size_t)blockIdx.x * 256 + threadIdx.x;
    if (i >= half) return;
    int n  = (int)(i & (N - 1));
    int k2 = (int)(i >> LOGN);
    float x0 = w[eW + ((size_t)(2 * k2)     << LOGN) + n];
    float x1 = w[eW + ((size_t)(2 * k2 + 1) << LOGN) + n];
    phi[eP + i] = pack_hi(x0, x1);
    plo[eP + i] = pack_lo(x0, x1);
}

// ---------------------------------------------------------------------------
// HMMA GEMM, pure cp.async pipeline (no in-loop conversions or STS).
// CTA 128x128, BK=32, 8 warps (2M x 4N), warp tile 64x32, 3 stages.
// Stage layout: Ahi[128][32]bf16(80B rows) | Alo | Bhi[16][128]u32(544B rows) | Blo
// ---------------------------------------------------------------------------
#define BK 32
#define A_ROWB 80
#define B_ROWB 544
#define ST_AHI 0
#define ST_ALO 10240
#define ST_BHI 20480
#define ST_BLO 29184
#define STAGE  37888

template<bool G1>
__global__ void __launch_bounds__(256, 1) gemm_mma(
    const uint32_t* __restrict__ bp_hi, const uint32_t* __restrict__ bp_lo,
    const float* __restrict__ x, float* __restrict__ out)
{
    constexpr int K   = G1 ? C_DIM : H_DIM;   // reduction dim
    constexpr int NBU = G1 ? H_DIM : C_DIM;   // B plane row width (uint32)
    constexpr int NC  = K / BK;

    int e     = blockIdx.z;
    int pbase = g_poff[e];
    int pcnt  = g_poff[e + 1] - pbase;
    int row0  = blockIdx.y * 128;
    if (row0 >= pcnt) return;
    int coln0 = blockIdx.x * 128;
    int prow0 = pbase + row0;

    extern __shared__ __align__(16) char sm[];
    uint32_t sb = smem_u32(sm);

    int tid = threadIdx.x, lane = tid & 31, wid = tid >> 5;
    int wm = wid & 1, wn = wid >> 1;
    int g4 = lane >> 2, t4 = lane & 3;

    int obase = g_offset[e];
    int cnt   = g_offset[e + 1] - obase;

    // ---- A cp.async sources: 2 rows per thread, one 16B chunk each ----
    int ar0 = tid >> 2, ar1 = 64 + (tid >> 2);
    int ak  = (tid & 3) * 8;                       // element offset within 32-k chunk
    const __nv_bfloat16 *ah0, *al0, *ah1, *al1;
    uint32_t sz0 = 16, sz1 = 16;
    if (G1) {
        int gr0 = row0 + ar0, gr1 = row0 + ar1;
        if (gr0 < cnt) {
            int tok = g_sorted[obase + gr0];
            ah0 = g_h_hi + (size_t)tok * C_DIM + ak;
            al0 = g_h_lo + (size_t)tok * C_DIM + ak;
        } else { ah0 = g_h_hi; al0 = g_h_lo; sz0 = 0; }
        if (gr1 < cnt) {
            int tok = g_sorted[obase + gr1];
            ah1 = g_h_hi + (size_t)tok * C_DIM + ak;
            al1 = g_h_lo + (size_t)tok * C_DIM + ak;
        } else { ah1 = g_h_hi; al1 = g_h_lo; sz1 = 0; }
    } else {
        ah0 = g_act_hi + (size_t)(prow0 + ar0) * H_DIM + ak;
        al0 = g_act_lo + (size_t)(prow0 + ar0) * H_DIM + ak;
        ah1 = g_act_hi + (size_t)(prow0 + ar1) * H_DIM + ak;
        al1 = g_act_lo + (size_t)(prow0 + ar1) * H_DIM + ak;
    }
    uint32_t a_dst0 = (uint32_t)(ar0 * A_ROWB + (tid & 3) * 16);
    uint32_t a_dst1 = (uint32_t)(ar1 * A_ROWB + (tid & 3) * 16);

    // ---- B cp.async sources: 2 k2-rows per thread, one 16B chunk each ----
    int brr0 = tid >> 5, brr1 = 8 + (tid >> 5);
    int bcu  = (tid & 31) * 4;                     // uint32 col within tile
    const uint32_t* bbase = bp_hi + (size_t)e * (K / 2) * NBU + coln0 + bcu;
    const uint32_t* lbase = bp_lo + (size_t)e * (K / 2) * NBU + coln0 + bcu;
    const uint32_t* bh0 = bbase + (size_t)brr0 * NBU;
    const uint32_t* bh1 = bbase + (size_t)brr1 * NBU;
    const uint32_t* bl0 = lbase + (size_t)brr0 * NBU;
    const uint32_t* bl1 = lbase + (size_t)brr1 * NBU;
    uint32_t b_dst0 = (uint32_t)(brr0 * B_ROWB + (tid & 31) * 16);
    uint32_t b_dst1 = (uint32_t)(brr1 * B_ROWB + (tid & 31) * 16);

    auto issue = [&](int c) {
        uint32_t st = sb + (uint32_t)(c % 3) * STAGE;
        int ko = c * BK;                           // A element offset
        size_t bko = (size_t)c * 16 * NBU;         // B uint32 offset (16 k2-rows/chunk)
        cp16s(st + ST_AHI + a_dst0, ah0 + ko, sz0);
        cp16s(st + ST_AHI + a_dst1, ah1 + ko, sz1);
        cp16s(st + ST_ALO + a_dst0, al0 + ko, sz0);
        cp16s(st + ST_ALO + a_dst1, al1 + ko, sz1);
        cp16(st + ST_BHI + b_dst0, bh0 + bko);
        cp16(st + ST_BHI + b_dst1, bh1 + bko);
        cp16(st + ST_BLO + b_dst0, bl0 + bko);
        cp16(st + ST_BLO + b_dst1, bl1 + bko);
        cp_commit();
    };

    float acc[4][4][4];
#pragma unroll
    for (int i = 0; i < 4; i++)
#pragma unroll
        for (int j = 0; j < 4; j++)
#pragma unroll
            for (int q = 0; q < 4; q++) acc[i][j][q] = 0.f;

    issue(0);
    issue(1);

#pragma unroll 1
    for (int c = 0; c < NC; c++) {
        if (c + 1 < NC) cp_wait1(); else cp_wait0();
        __syncthreads();
        if (c + 2 < NC) issue(c + 2);   // stage (c+2)%3 == (c-1)%3: readers done pre-sync

        uint32_t st = sb + (uint32_t)(c % 3) * STAGE;
#pragma unroll
        for (int ks = 0; ks < 2; ks++) {
            uint32_t ahi[4][4], alo[4][4];
#pragma unroll
            for (int mi = 0; mi < 4; mi++) {
                uint32_t base = st + (uint32_t)((wm * 64 + mi * 16 + g4) * A_ROWB + ks * 32 + t4 * 4);
                ahi[mi][0] = lds32(base);
                ahi[mi][1] = lds32(base + 8 * A_ROWB);
                ahi[mi][2] = lds32(base + 16);
                ahi[mi][3] = lds32(base + 8 * A_ROWB + 16);
                uint32_t basel = base + ST_ALO;
                alo[mi][0] = lds32(basel);
                alo[mi][1] = lds32(basel + 8 * A_ROWB);
                alo[mi][2] = lds32(basel + 16);
                alo[mi][3] = lds32(basel + 8 * A_ROWB + 16);
            }
            uint32_t bhi[4][2], blo[4][2];
#pragma unroll
            for (int nt = 0; nt < 4; nt++) {
                uint32_t n4 = (uint32_t)((wn * 32 + nt * 8 + g4) * 4);
                uint32_t bb = st + ST_BHI + (uint32_t)((ks * 8 + t4) * B_ROWB) + n4;
                bhi[nt][0] = lds32(bb);
                bhi[nt][1] = lds32(bb + 4 * B_ROWB);
                uint32_t bbl = bb + (ST_BLO - ST_BHI);
                blo[nt][0] = lds32(bbl);
                blo[nt][1] = lds32(bbl + 4 * B_ROWB);
            }
#pragma unroll
            for (int mi = 0; mi < 4; mi++)
#pragma unroll
                for (int nt = 0; nt < 4; nt++) {
                    float* cc = acc[mi][nt];
                    mma16816(cc, ahi[mi], bhi[nt][0], bhi[nt][1]);
                    mma16816(cc, alo[mi], bhi[nt][0], bhi[nt][1]);
                    mma16816(cc, ahi[mi], blo[nt][0], blo[nt][1]);
                }
        }
    }

    // ---- epilogue ----
    if (G1) {
#pragma unroll
        for (int mi = 0; mi < 4; mi++) {
            int gr = wm * 64 + mi * 16 + g4;
            size_t r0g = (size_t)(prow0 + gr)     * H_DIM;
            size_t r1g = (size_t)(prow0 + gr + 8) * H_DIM;
#pragma unroll
            for (int nt = 0; nt < 4; nt++) {
                int gc = coln0 + wn * 32 + nt * 8 + t4 * 2;
                float* cc = acc[mi][nt];
                float v0x = fmaxf(cc[0], 0.f); v0x *= v0x;
                float v0y = fmaxf(cc[1], 0.f); v0y *= v0y;
                float v1x = fmaxf(cc[2], 0.f); v1x *= v1x;
                float v1y = fmaxf(cc[3], 0.f); v1y *= v1y;
                *reinterpret_cast<uint32_t*>(g_act_hi + r0g + gc) = pack_hi(v0x, v0y);
                *reinterpret_cast<uint32_t*>(g_act_lo + r0g + gc) = pack_lo(v0x, v0y);
                *reinterpret_cast<uint32_t*>(g_act_hi + r1g + gc) = pack_hi(v1x, v1y);
                *reinterpret_cast<uint32_t*>(g_act_lo + r1g + gc) = pack_lo(v1x, v1y);
            }
        }
    } else {
#pragma unroll
        for (int mi = 0; mi < 4; mi++) {
            int rl0 = row0 + wm * 64 + mi * 16 + g4;
            int tok0 = -1, tok1 = -1;
            float sc0 = 0.f, sc1 = 0.f;
            if (rl0 < cnt)     { tok0 = g_sorted[obase + rl0];     sc0 = g_scale[tok0]; }
            if (rl0 + 8 < cnt) { tok1 = g_sorted[obase + rl0 + 8]; sc1 = g_scale[tok1]; }
#pragma unroll
            for (int nt = 0; nt < 4; nt++) {
                int gc = coln0 + wn * 32 + nt * 8 + t4 * 2;
                float* cc = acc[mi][nt];
                if (tok0 >= 0) {
                    size_t o = (size_t)tok0 * C_DIM + gc;
                    float2 xv = *reinterpret_cast<const float2*>(x + o);
                    float2 ov; ov.x = xv.x + cc[0] * sc0; ov.y = xv.y + cc[1] * sc0;
                    *reinterpret_cast<float2*>(out + o) = ov;
                }
                if (tok1 >= 0) {
                    size_t o = (size_t)tok1 * C_DIM + gc;
                    float2 xv = *reinterpret_cast<const float2*>(x + o);
                    float2 ov; ov.x = xv.x + cc[2] * sc1; ov.y = xv.y + cc[3] * sc1;
                    *reinterpret_cast<float2*>(out + o) = ov;
                }
            }
        }
    }
}

// ---------------------------------------------------------------------------
extern "C" void kernel_launch(void* const* d_in, const int* in_sizes, int n_in,
                              void* d_out, int out_size)
{
    const float* x       = (const float*)d_in[0];
    const int*   winners = (const int*)  d_in[1];
    const float* gamma   = (const float*)d_in[2];
    const float* beta    = (const float*)d_in[3];
    const float* w1      = (const float*)d_in[4];
    const float* w2      = (const float*)d_in[5];
    const float* wc      = (const float*)d_in[6];
    const float* bc      = (const float*)d_in[7];
    float* out = (float*)d_out;

    const int SMEM = 3 * STAGE;   // 113664 B
    cudaFuncSetAttribute(gemm_mma<true>,  cudaFuncAttributeMaxDynamicSharedMemorySize, SMEM);
    cudaFuncSetAttribute(gemm_mma<false>, cudaFuncAttributeMaxDynamicSharedMemorySize, SMEM);

    init_kernel<<<1, 32>>>();
    ln_conf_kernel<<<N_TOK, 256>>>(x, winners, gamma, beta, wc, bc);
    scan_kernel<<<1, 32>>>();
    scatter_kernel<<<N_TOK / 256, 256>>>(winners);

    // weight pack: w1 K=C, N=H (logN=12); w2 K=H, N=C (logN=10)
    conv_w<12><<<dim3((unsigned)(((size_t)(C_DIM / 2) * H_DIM + 255) / 256), 1, E_NUM), 256>>>(
        w1, g_w1p_hi, g_w1p_lo, C_DIM);
    conv_w<10><<<dim3((unsigned)(((size_t)(H_DIM / 2) * C_DIM + 255) / 256), 1, E_NUM), 256>>>(
        w2, g_w2p_hi, g_w2p_lo, H_DIM);

    gemm_mma<true><<<dim3(H_DIM / 128, PADDED_CAP / 128, E_NUM), 256, SMEM>>>(
        g_w1p_hi, g_w1p_lo, x, out);
    gemm_mma<false><<<dim3(C_DIM / 128, PADDED_CAP / 128, E_NUM), 256, SMEM>>>(
        g_w2p_hi, g_w2p_lo, x, out);
}

// round 9
// speedup vs baseline: 7.7618x; 7.7618x over previous
#include <cuda_runtime.h>
#include <cuda_bf16.h>
#include <stdint.h>
#include <math.h>

#define N_TOK 8192
#define C_DIM 1024
#define H_DIM 4096
#define E_NUM 5
#define PADDED_CAP (N_TOK + E_NUM * 128)   // 8832

// ---------------------------------------------------------------------------
// Device scratch (allocation-free per harness rules)
// ---------------------------------------------------------------------------
__device__ float g_h[(size_t)N_TOK * C_DIM];                       // layernormed tokens (fp32)
__device__ float g_act[(size_t)PADDED_CAP * H_DIM];                // relu^2 activations (fp32)
__device__ float g_scale[N_TOK];
__device__ int   g_sorted[N_TOK];
__device__ int   g_count[E_NUM];
__device__ int   g_offset[E_NUM + 1];
__device__ int   g_poff[E_NUM + 1];
__device__ int   g_cursor[E_NUM];

// ---------------------------------------------------------------------------
// PTX helpers
// ---------------------------------------------------------------------------
__device__ __forceinline__ uint32_t smem_u32(const void* p) {
    uint32_t a;
    asm("{ .reg .u64 t; cvta.to.shared.u64 t, %1; cvt.u32.u64 %0, t; }" : "=r"(a) : "l"(p));
    return a;
}
__device__ __forceinline__ void lds64(uint32_t& h, uint32_t& l, uint32_t a) {
    asm volatile("ld.shared.v2.u32 {%0,%1}, [%2];" : "=r"(h), "=r"(l) : "r"(a));
}
__device__ __forceinline__ void mma16816(float* c, const uint32_t* a, uint32_t b0, uint32_t b1) {
    asm volatile("mma.sync.aligned.m16n8k16.row.col.f32.bf16.bf16.f32 "
                 "{%0,%1,%2,%3}, {%4,%5,%6,%7}, {%8,%9}, {%0,%1,%2,%3};"
                 : "+f"(c[0]), "+f"(c[1]), "+f"(c[2]), "+f"(c[3])
                 : "r"(a[0]), "r"(a[1]), "r"(a[2]), "r"(a[3]), "r"(b0), "r"(b1));
}
__device__ __forceinline__ uint32_t pack_hi(float x, float y) {
    __nv_bfloat162 p; p.x = __float2bfloat16(x); p.y = __float2bfloat16(y);
    return *reinterpret_cast<uint32_t*>(&p);
}
__device__ __forceinline__ uint32_t pack_lo(float x, float y) {
    __nv_bfloat16 hx = __float2bfloat16(x), hy = __float2bfloat16(y);
    __nv_bfloat162 p;
    p.x = __float2bfloat16(x - __bfloat162float(hx));
    p.y = __float2bfloat16(y - __bfloat162float(hy));
    return *reinterpret_cast<uint32_t*>(&p);
}

// ---------------------------------------------------------------------------
// Small pipeline kernels (validated)
// ---------------------------------------------------------------------------
__global__ void init_kernel() {
    if (threadIdx.x < E_NUM) { g_count[threadIdx.x] = 0; g_cursor[threadIdx.x] = 0; }
}

__global__ void __launch_bounds__(256) ln_conf_kernel(
    const float* __restrict__ x, const int* __restrict__ winners,
    const float* __restrict__ gamma, const float* __restrict__ beta,
    const float* __restrict__ wc, const float* __restrict__ bc)
{
    int n = blockIdx.x, tid = threadIdx.x;
    const float* xr = x + (size_t)n * C_DIM;
    float xv[4], s = 0.f, s2 = 0.f;
#pragma unroll
    for (int i = 0; i < 4; i++) { float v = xr[tid + 256 * i]; xv[i] = v; s += v; s2 += v * v; }
#pragma unroll
    for (int off = 16; off > 0; off >>= 1) {
        s  += __shfl_down_sync(0xffffffffu, s,  off);
        s2 += __shfl_down_sync(0xffffffffu, s2, off);
    }
    __shared__ float sh1[8], sh2[8];
    __shared__ float s_mean, s_rstd;
    int warp = tid >> 5, lane = tid & 31;
    if (lane == 0) { sh1[warp] = s; sh2[warp] = s2; }
    __syncthreads();
    if (tid == 0) {
        float ts = 0.f, ts2 = 0.f;
#pragma unroll
        for (int w = 0; w < 8; w++) { ts += sh1[w]; ts2 += sh2[w]; }
        float mean = ts * (1.f / C_DIM);
        float var = ts2 * (1.f / C_DIM) - mean * mean;
        s_mean = mean; s_rstd = rsqrtf(var + 1e-5f);
    }
    __syncthreads();
    float mean = s_mean, rstd = s_rstd;
    int win = winners[n];
    const float* wcr = wc + (size_t)win * C_DIM;
    float dot = 0.f;
#pragma unroll
    for (int i = 0; i < 4; i++) {
        int c = tid + 256 * i;
        float hv = (xv[i] - mean) * rstd * gamma[c] + beta[c];
        g_h[(size_t)n * C_DIM + c] = hv;
        dot += hv * wcr[c];
    }
#pragma unroll
    for (int off = 16; off > 0; off >>= 1) dot += __shfl_down_sync(0xffffffffu, dot, off);
    if (lane == 0) sh1[warp] = dot;
    __syncthreads();
    if (tid == 0) {
        float t = 0.f;
#pragma unroll
        for (int w = 0; w < 8; w++) t += sh1[w];
        t += bc[win];
        float conf = 1.f / (1.f + expf(-t));
        g_scale[n] = conf / (conf + 1e-6f);
        atomicAdd(&g_count[win], 1);
    }
}

__global__ void scan_kernel() {
    if (threadIdx.x == 0) {
        int acc = 0, pacc = 0;
        g_offset[0] = 0; g_poff[0] = 0;
        for (int e = 0; e < E_NUM; e++) {
            int c = g_count[e];
            acc += c;
            g_offset[e + 1] = acc;
            g_cursor[e] = g_offset[e];
            pacc += ((c + 127) / 128) * 128;
            g_poff[e + 1] = pacc;
        }
    }
}

__global__ void scatter_kernel(const int* __restrict__ winners) {
    int n = blockIdx.x * blockDim.x + threadIdx.x;
    if (n < N_TOK) {
        int e = winners[n];
        int pos = atomicAdd(&g_cursor[e], 1);
        g_sorted[pos] = n;
    }
}

// ---------------------------------------------------------------------------
// HMMA GEMM (R7 structure; interleaved hi/lo smem -> LDS.64 fragment loads).
// CTA 128x128, BK=32, 8 warps (2M x 4N), warp tile 64x32, double-buffered.
// A plane: [m 0..127][k-pair 0..15] slots of 8B (hi_u32, lo_u32), row 160B.
// B plane: [k2 0..15][n 0..127]     slots of 8B (hi_u32, lo_u32), row 1056B.
// Weights read DIRECTLY from harness w pointers (device-global staging is
// a proven 8-11x regression on this setup — R6/R8).
// ---------------------------------------------------------------------------
#define BK 32
#define A_ROWB 160
#define B_ROWB 1056
#define ST_A   0
#define ST_B   20480                  // 128 * 160
#define STAGE  37376                  // 20480 + 16 * 1056

template<bool G1>
__global__ void __launch_bounds__(256, 1) gemm_mma(
    const float* __restrict__ w,      // G1: w1 [E][C][H]; G2: w2 [E][H][C]
    const float* __restrict__ x,
    float* __restrict__ out)
{
    constexpr int K  = G1 ? C_DIM : H_DIM;   // reduction dim
    constexpr int NB = G1 ? H_DIM : C_DIM;   // output-feature dim
    constexpr int NC = K / BK;

    int e     = blockIdx.z;
    int pbase = g_poff[e];
    int pcnt  = g_poff[e + 1] - pbase;
    int row0  = blockIdx.y * 128;
    if (row0 >= pcnt) return;
    int coln0 = blockIdx.x * 128;
    int prow0 = pbase + row0;

    extern __shared__ __align__(16) char sm[];
    uint32_t sb = smem_u32(sm);

    int tid = threadIdx.x, lane = tid & 31, wid = tid >> 5;
    int wm = wid & 1, wn = wid >> 1;
    int g4 = lane >> 2, t4 = lane & 3;

    int obase = g_offset[e];
    int cnt   = g_offset[e + 1] - obase;

    // ---- A source rows: 4 rows per thread, k-quarter kq ----
    int kq = tid & 7;
    const float* asrc[4];
#pragma unroll
    for (int p = 0; p < 4; p++) {
        int m = p * 32 + (tid >> 3);
        if (G1) {
            int gr = row0 + m;
            asrc[p] = (gr < cnt) ? (g_h + (size_t)g_sorted[obase + gr] * C_DIM) : 0;
        } else {
            asrc[p] = g_act + (size_t)(prow0 + m) * H_DIM;
        }
    }
    // ---- B source: one n column per thread, coalesced across lanes ----
    int nb = tid & 127;
    int khalf = tid >> 7;             // 0/1
    const float* bcol = w + (size_t)e * C_DIM * H_DIM + (coln0 + nb);

    float acc[4][4][4];
#pragma unroll
    for (int i = 0; i < 4; i++)
#pragma unroll
        for (int j = 0; j < 4; j++)
#pragma unroll
            for (int q = 0; q < 4; q++) acc[i][j][q] = 0.f;

    // register prefetch buffers
    float4 ra[4];
    float  rb0[8], rb1[8];

    // STS: interleaved hi/lo slots
    auto sts_chunk = [&](uint32_t soff) {
#pragma unroll
        for (int p = 0; p < 4; p++) {
            int m = p * 32 + (tid >> 3);
            uint32_t off = soff + ST_A + (uint32_t)(m * A_ROWB + kq * 16);
            uint4 v;
            v.x = pack_hi(ra[p].x, ra[p].y);
            v.y = pack_lo(ra[p].x, ra[p].y);
            v.z = pack_hi(ra[p].z, ra[p].w);
            v.w = pack_lo(ra[p].z, ra[p].w);
            *reinterpret_cast<uint4*>(sm + off) = v;
        }
#pragma unroll
        for (int p = 0; p < 8; p++) {
            int kp = p * 2 + khalf;
            uint32_t off = soff + ST_B + (uint32_t)(kp * B_ROWB + nb * 8);
            uint2 v;
            v.x = pack_hi(rb0[p], rb1[p]);
            v.y = pack_lo(rb0[p], rb1[p]);
            *reinterpret_cast<uint2*>(sm + off) = v;
        }
    };
    auto ldg_chunk = [&](int c) {
        int k0 = c * BK;
#pragma unroll
        for (int p = 0; p < 4; p++)
            ra[p] = asrc[p] ? *reinterpret_cast<const float4*>(asrc[p] + k0 + 4 * kq)
                            : make_float4(0.f, 0.f, 0.f, 0.f);
#pragma unroll
        for (int p = 0; p < 8; p++) {
            int k = k0 + 2 * (p * 2 + khalf);
            rb0[p] = bcol[(size_t)k * NB];
            rb1[p] = bcol[(size_t)(k + 1) * NB];
        }
    };

    // prologue: chunk0 -> stage0; prefetch chunk1 into regs
    ldg_chunk(0);
    sts_chunk(0);
    if (NC > 1) ldg_chunk(1);
    __syncthreads();

#pragma unroll 1
    for (int c = 0; c < NC; c++) {
        uint32_t st = sb + (uint32_t)(c & 1) * STAGE;

        // ---- compute chunk c ----
#pragma unroll
        for (int ks = 0; ks < 2; ks++) {
            uint32_t ahi[4][4], alo[4][4];
#pragma unroll
            for (int mi = 0; mi < 4; mi++) {
                uint32_t base = st + ST_A
                    + (uint32_t)((wm * 64 + mi * 16 + g4) * A_ROWB + (ks * 8 + t4) * 8);
                lds64(ahi[mi][0], alo[mi][0], base);
                lds64(ahi[mi][1], alo[mi][1], base + 8 * A_ROWB);
                lds64(ahi[mi][2], alo[mi][2], base + 32);
                lds64(ahi[mi][3], alo[mi][3], base + 8 * A_ROWB + 32);
            }
            uint32_t bhi[4][2], blo[4][2];
#pragma unroll
            for (int nt = 0; nt < 4; nt++) {
                uint32_t bb = st + ST_B
                    + (uint32_t)((ks * 8 + t4) * B_ROWB + (wn * 32 + nt * 8 + g4) * 8);
                lds64(bhi[nt][0], blo[nt][0], bb);
                lds64(bhi[nt][1], blo[nt][1], bb + 4 * B_ROWB);
            }
#pragma unroll
            for (int mi = 0; mi < 4; mi++)
#pragma unroll
                for (int nt = 0; nt < 4; nt++) {
                    float* cc = acc[mi][nt];
                    mma16816(cc, ahi[mi], bhi[nt][0], bhi[nt][1]);
                    mma16816(cc, alo[mi], bhi[nt][0], bhi[nt][1]);
                    mma16816(cc, ahi[mi], blo[nt][0], blo[nt][1]);
                }
        }

        // ---- stage chunk c+1 into the other buffer, prefetch c+2 ----
        if (c + 1 < NC) {
            sts_chunk((uint32_t)((c + 1) & 1) * STAGE);
            if (c + 2 < NC) ldg_chunk(c + 2);
            __syncthreads();
        }
    }

    // ---- epilogue (unchanged) ----
    if (G1) {
#pragma unroll
        for (int mi = 0; mi < 4; mi++) {
            int gr = wm * 64 + mi * 16 + g4;
            size_t r0g = (size_t)(prow0 + gr)     * H_DIM;
            size_t r1g = (size_t)(prow0 + gr + 8) * H_DIM;
#pragma unroll
            for (int nt = 0; nt < 4; nt++) {
                int gc = coln0 + wn * 32 + nt * 8 + t4 * 2;
                float* cc = acc[mi][nt];
                float2 v0, v1;
                v0.x = fmaxf(cc[0], 0.f); v0.x *= v0.x;
                v0.y = fmaxf(cc[1], 0.f); v0.y *= v0.y;
                v1.x = fmaxf(cc[2], 0.f); v1.x *= v1.x;
                v1.y = fmaxf(cc[3], 0.f); v1.y *= v1.y;
                *reinterpret_cast<float2*>(g_act + r0g + gc) = v0;
                *reinterpret_cast<float2*>(g_act + r1g + gc) = v1;
            }
        }
    } else {
#pragma unroll
        for (int mi = 0; mi < 4; mi++) {
            int rl0 = row0 + wm * 64 + mi * 16 + g4;
            int tok0 = -1, tok1 = -1;
            float sc0 = 0.f, sc1 = 0.f;
            if (rl0 < cnt)     { tok0 = g_sorted[obase + rl0];     sc0 = g_scale[tok0]; }
            if (rl0 + 8 < cnt) { tok1 = g_sorted[obase + rl0 + 8]; sc1 = g_scale[tok1]; }
#pragma unroll
            for (int nt = 0; nt < 4; nt++) {
                int gc = coln0 + wn * 32 + nt * 8 + t4 * 2;
                float* cc = acc[mi][nt];
                if (tok0 >= 0) {
                    size_t o = (size_t)tok0 * C_DIM + gc;
                    float2 xv = *reinterpret_cast<const float2*>(x + o);
                    float2 ov; ov.x = xv.x + cc[0] * sc0; ov.y = xv.y + cc[1] * sc0;
                    *reinterpret_cast<float2*>(out + o) = ov;
                }
                if (tok1 >= 0) {
                    size_t o = (size_t)tok1 * C_DIM + gc;
                    float2 xv = *reinterpret_cast<const float2*>(x + o);
                    float2 ov; ov.x = xv.x + cc[2] * sc1; ov.y = xv.y + cc[3] * sc1;
                    *reinterpret_cast<float2*>(out + o) = ov;
                }
            }
        }
    }
}

// ---------------------------------------------------------------------------
extern "C" void kernel_launch(void* const* d_in, const int* in_sizes, int n_in,
                              void* d_out, int out_size)
{
    const float* x       = (const float*)d_in[0];
    const int*   winners = (const int*)  d_in[1];
    const float* gamma   = (const float*)d_in[2];
    const float* beta    = (const float*)d_in[3];
    const float* w1      = (const float*)d_in[4];
    const float* w2      = (const float*)d_in[5];
    const float* wc      = (const float*)d_in[6];
    const float* bc      = (const float*)d_in[7];
    float* out = (float*)d_out;

    const int SMEM = 2 * STAGE;   // 74752 B dynamic
    cudaFuncSetAttribute(gemm_mma<true>,  cudaFuncAttributeMaxDynamicSharedMemorySize, SMEM);
    cudaFuncSetAttribute(gemm_mma<false>, cudaFuncAttributeMaxDynamicSharedMemorySize, SMEM);

    init_kernel<<<1, 32>>>();
    ln_conf_kernel<<<N_TOK, 256>>>(x, winners, gamma, beta, wc, bc);
    scan_kernel<<<1, 32>>>();
    scatter_kernel<<<N_TOK / 256, 256>>>(winners);

    gemm_mma<true><<<dim3(H_DIM / 128, PADDED_CAP / 128, E_NUM), 256, SMEM>>>(w1, x, out);
    gemm_mma<false><<<dim3(C_DIM / 128, PADDED_CAP / 128, E_NUM), 256, SMEM>>>(w2, x, out);
}

// round 10
// speedup vs baseline: 7.9196x; 1.0203x over previous
#include <cuda_runtime.h>
#include <cuda_bf16.h>
#include <stdint.h>
#include <math.h>

#define N_TOK 8192
#define C_DIM 1024
#define H_DIM 4096
#define E_NUM 5
#define PADDED_CAP (N_TOK + E_NUM * 128)   // 8832

// ---------------------------------------------------------------------------
// Device scratch (allocation-free per harness rules)
// ---------------------------------------------------------------------------
__device__ float g_h[(size_t)N_TOK * C_DIM];                       // layernormed tokens (fp32)
__device__ float g_act[(size_t)PADDED_CAP * H_DIM];                // relu^2 activations (fp32)
__device__ float g_scale[N_TOK];
__device__ int   g_sorted[N_TOK];
__device__ int   g_count[E_NUM];
__device__ int   g_offset[E_NUM + 1];
__device__ int   g_poff[E_NUM + 1];
__device__ int   g_cursor[E_NUM];

// ---------------------------------------------------------------------------
// PTX helpers
// ---------------------------------------------------------------------------
__device__ __forceinline__ uint32_t smem_u32(const void* p) {
    uint32_t a;
    asm("{ .reg .u64 t; cvta.to.shared.u64 t, %1; cvt.u32.u64 %0, t; }" : "=r"(a) : "l"(p));
    return a;
}
__device__ __forceinline__ void lds64(uint32_t& h, uint32_t& l, uint32_t a) {
    asm volatile("ld.shared.v2.u32 {%0,%1}, [%2];" : "=r"(h), "=r"(l) : "r"(a));
}
__device__ __forceinline__ void mma16816(float* c, const uint32_t* a, uint32_t b0, uint32_t b1) {
    asm volatile("mma.sync.aligned.m16n8k16.row.col.f32.bf16.bf16.f32 "
                 "{%0,%1,%2,%3}, {%4,%5,%6,%7}, {%8,%9}, {%0,%1,%2,%3};"
                 : "+f"(c[0]), "+f"(c[1]), "+f"(c[2]), "+f"(c[3])
                 : "r"(a[0]), "r"(a[1]), "r"(a[2]), "r"(a[3]), "r"(b0), "r"(b1));
}
__device__ __forceinline__ uint32_t pack_hi(float x, float y) {
    __nv_bfloat162 p; p.x = __float2bfloat16(x); p.y = __float2bfloat16(y);
    return *reinterpret_cast<uint32_t*>(&p);
}
__device__ __forceinline__ uint32_t pack_lo(float x, float y) {
    __nv_bfloat16 hx = __float2bfloat16(x), hy = __float2bfloat16(y);
    __nv_bfloat162 p;
    p.x = __float2bfloat16(x - __bfloat162float(hx));
    p.y = __float2bfloat16(y - __bfloat162float(hy));
    return *reinterpret_cast<uint32_t*>(&p);
}

// ---------------------------------------------------------------------------
// Small pipeline kernels (validated)
// ---------------------------------------------------------------------------
__global__ void init_kernel() {
    if (threadIdx.x < E_NUM) { g_count[threadIdx.x] = 0; g_cursor[threadIdx.x] = 0; }
}

__global__ void __launch_bounds__(256) ln_conf_kernel(
    const float* __restrict__ x, const int* __restrict__ winners,
    const float* __restrict__ gamma, const float* __restrict__ beta,
    const float* __restrict__ wc, const float* __restrict__ bc)
{
    int n = blockIdx.x, tid = threadIdx.x;
    const float* xr = x + (size_t)n * C_DIM;
    float xv[4], s = 0.f, s2 = 0.f;
#pragma unroll
    for (int i = 0; i < 4; i++) { float v = xr[tid + 256 * i]; xv[i] = v; s += v; s2 += v * v; }
#pragma unroll
    for (int off = 16; off > 0; off >>= 1) {
        s  += __shfl_down_sync(0xffffffffu, s,  off);
        s2 += __shfl_down_sync(0xffffffffu, s2, off);
    }
    __shared__ float sh1[8], sh2[8];
    __shared__ float s_mean, s_rstd;
    int warp = tid >> 5, lane = tid & 31;
    if (lane == 0) { sh1[warp] = s; sh2[warp] = s2; }
    __syncthreads();
    if (tid == 0) {
        float ts = 0.f, ts2 = 0.f;
#pragma unroll
        for (int w = 0; w < 8; w++) { ts += sh1[w]; ts2 += sh2[w]; }
        float mean = ts * (1.f / C_DIM);
        float var = ts2 * (1.f / C_DIM) - mean * mean;
        s_mean = mean; s_rstd = rsqrtf(var + 1e-5f);
    }
    __syncthreads();
    float mean = s_mean, rstd = s_rstd;
    int win = winners[n];
    const float* wcr = wc + (size_t)win * C_DIM;
    float dot = 0.f;
#pragma unroll
    for (int i = 0; i < 4; i++) {
        int c = tid + 256 * i;
        float hv = (xv[i] - mean) * rstd * gamma[c] + beta[c];
        g_h[(size_t)n * C_DIM + c] = hv;
        dot += hv * wcr[c];
    }
#pragma unroll
    for (int off = 16; off > 0; off >>= 1) dot += __shfl_down_sync(0xffffffffu, dot, off);
    if (lane == 0) sh1[warp] = dot;
    __syncthreads();
    if (tid == 0) {
        float t = 0.f;
#pragma unroll
        for (int w = 0; w < 8; w++) t += sh1[w];
        t += bc[win];
        float conf = 1.f / (1.f + expf(-t));
        g_scale[n] = conf / (conf + 1e-6f);
        atomicAdd(&g_count[win], 1);
    }
}

__global__ void scan_kernel() {
    if (threadIdx.x == 0) {
        int acc = 0, pacc = 0;
        g_offset[0] = 0; g_poff[0] = 0;
        for (int e = 0; e < E_NUM; e++) {
            int c = g_count[e];
            acc += c;
            g_offset[e + 1] = acc;
            g_cursor[e] = g_offset[e];
            pacc += ((c + 127) / 128) * 128;
            g_poff[e + 1] = pacc;
        }
    }
}

__global__ void scatter_kernel(const int* __restrict__ winners) {
    int n = blockIdx.x * blockDim.x + threadIdx.x;
    if (n < N_TOK) {
        int e = winners[n];
        int pos = atomicAdd(&g_cursor[e], 1);
        g_sorted[pos] = n;
    }
}

// ---------------------------------------------------------------------------
// HMMA GEMM: CTA 128x128, BK=32, 16 warps (4M x 4N), warp tile 32x32.
// Double-buffered smem, interleaved hi/lo 8B slots (R9 layout), weights read
// directly from harness pointers (device-global weight staging = 8-11x
// regression, R6/R8). 4 warps per SMSP for latency hiding.
// ---------------------------------------------------------------------------
#define BK 32
#define A_ROWB 160
#define B_ROWB 1056
#define ST_A   0
#define ST_B   20480                  // 128 * 160
#define STAGE  37376                  // 20480 + 16 * 1056

template<bool G1>
__global__ void __launch_bounds__(512, 1) gemm_mma(
    const float* __restrict__ w,      // G1: w1 [E][C][H]; G2: w2 [E][H][C]
    const float* __restrict__ x,
    float* __restrict__ out)
{
    constexpr int K  = G1 ? C_DIM : H_DIM;   // reduction dim
    constexpr int NB = G1 ? H_DIM : C_DIM;   // output-feature dim
    constexpr int NC = K / BK;

    int e     = blockIdx.z;
    int pbase = g_poff[e];
    int pcnt  = g_poff[e + 1] - pbase;
    int row0  = blockIdx.y * 128;
    if (row0 >= pcnt) return;
    int coln0 = blockIdx.x * 128;
    int prow0 = pbase + row0;

    extern __shared__ __align__(16) char sm[];
    uint32_t sb = smem_u32(sm);

    int tid = threadIdx.x, lane = tid & 31, wid = tid >> 5;
    int wm = wid & 3, wn = wid >> 2;         // 4M x 4N warp grid
    int g4 = lane >> 2, t4 = lane & 3;

    int obase = g_offset[e];
    int cnt   = g_offset[e + 1] - obase;

    // ---- A source rows: 2 rows per thread, k-quarter kq ----
    int kq = tid & 7;
    const float* asrc[2];
#pragma unroll
    for (int p = 0; p < 2; p++) {
        int m = p * 64 + (tid >> 3);
        if (G1) {
            int gr = row0 + m;
            asrc[p] = (gr < cnt) ? (g_h + (size_t)g_sorted[obase + gr] * C_DIM) : 0;
        } else {
            asrc[p] = g_act + (size_t)(prow0 + m) * H_DIM;
        }
    }
    // ---- B source: one n column per thread, 4 k-pairs (kp = p*4 + kq4) ----
    int nb = tid & 127;
    int kq4 = tid >> 7;               // 0..3
    const float* bcol = w + (size_t)e * C_DIM * H_DIM + (coln0 + nb);

    float acc[2][4][4];
#pragma unroll
    for (int i = 0; i < 2; i++)
#pragma unroll
        for (int j = 0; j < 4; j++)
#pragma unroll
            for (int q = 0; q < 4; q++) acc[i][j][q] = 0.f;

    // register prefetch buffers
    float4 ra[2];
    float  rb0[4], rb1[4];

    auto sts_chunk = [&](uint32_t soff) {
#pragma unroll
        for (int p = 0; p < 2; p++) {
            int m = p * 64 + (tid >> 3);
            uint32_t off = soff + ST_A + (uint32_t)(m * A_ROWB + kq * 16);
            uint4 v;
            v.x = pack_hi(ra[p].x, ra[p].y);
            v.y = pack_lo(ra[p].x, ra[p].y);
            v.z = pack_hi(ra[p].z, ra[p].w);
            v.w = pack_lo(ra[p].z, ra[p].w);
            *reinterpret_cast<uint4*>(sm + off) = v;
        }
#pragma unroll
        for (int p = 0; p < 4; p++) {
            int kp = p * 4 + kq4;
            uint32_t off = soff + ST_B + (uint32_t)(kp * B_ROWB + nb * 8);
            uint2 v;
            v.x = pack_hi(rb0[p], rb1[p]);
            v.y = pack_lo(rb0[p], rb1[p]);
            *reinterpret_cast<uint2*>(sm + off) = v;
        }
    };
    auto ldg_chunk = [&](int c) {
        int k0 = c * BK;
#pragma unroll
        for (int p = 0; p < 2; p++)
            ra[p] = asrc[p] ? *reinterpret_cast<const float4*>(asrc[p] + k0 + 4 * kq)
                            : make_float4(0.f, 0.f, 0.f, 0.f);
#pragma unroll
        for (int p = 0; p < 4; p++) {
            int k = k0 + 2 * (p * 4 + kq4);
            rb0[p] = bcol[(size_t)k * NB];
            rb1[p] = bcol[(size_t)(k + 1) * NB];
        }
    };

    // prologue: chunk0 -> stage0; prefetch chunk1 into regs
    ldg_chunk(0);
    sts_chunk(0);
    if (NC > 1) ldg_chunk(1);
    __syncthreads();

#pragma unroll 1
    for (int c = 0; c < NC; c++) {
        uint32_t st = sb + (uint32_t)(c & 1) * STAGE;

        // ---- compute chunk c ----
#pragma unroll
        for (int ks = 0; ks < 2; ks++) {
            uint32_t ahi[2][4], alo[2][4];
#pragma unroll
            for (int mi = 0; mi < 2; mi++) {
                uint32_t base = st + ST_A
                    + (uint32_t)((wm * 32 + mi * 16 + g4) * A_ROWB + (ks * 8 + t4) * 8);
                lds64(ahi[mi][0], alo[mi][0], base);
                lds64(ahi[mi][1], alo[mi][1], base + 8 * A_ROWB);
                lds64(ahi[mi][2], alo[mi][2], base + 32);
                lds64(ahi[mi][3], alo[mi][3], base + 8 * A_ROWB + 32);
            }
            uint32_t bhi[4][2], blo[4][2];
#pragma unroll
            for (int nt = 0; nt < 4; nt++) {
                uint32_t bb = st + ST_B
                    + (uint32_t)((ks * 8 + t4) * B_ROWB + (wn * 32 + nt * 8 + g4) * 8);
                lds64(bhi[nt][0], blo[nt][0], bb);
                lds64(bhi[nt][1], blo[nt][1], bb + 4 * B_ROWB);
            }
#pragma unroll
            for (int mi = 0; mi < 2; mi++)
#pragma unroll
                for (int nt = 0; nt < 4; nt++) {
                    float* cc = acc[mi][nt];
                    mma16816(cc, ahi[mi], bhi[nt][0], bhi[nt][1]);
                    mma16816(cc, alo[mi], bhi[nt][0], bhi[nt][1]);
                    mma16816(cc, ahi[mi], blo[nt][0], blo[nt][1]);
                }
        }

        // ---- stage chunk c+1 into the other buffer, prefetch c+2 ----
        if (c + 1 < NC) {
            sts_chunk((uint32_t)((c + 1) & 1) * STAGE);
            if (c + 2 < NC) ldg_chunk(c + 2);
            __syncthreads();
        }
    }

    // ---- epilogue ----
    if (G1) {
#pragma unroll
        for (int mi = 0; mi < 2; mi++) {
            int gr = wm * 32 + mi * 16 + g4;
            size_t r0g = (size_t)(prow0 + gr)     * H_DIM;
            size_t r1g = (size_t)(prow0 + gr + 8) * H_DIM;
#pragma unroll
            for (int nt = 0; nt < 4; nt++) {
                int gc = coln0 + wn * 32 + nt * 8 + t4 * 2;
                float* cc = acc[mi][nt];
                float2 v0, v1;
                v0.x = fmaxf(cc[0], 0.f); v0.x *= v0.x;
                v0.y = fmaxf(cc[1], 0.f); v0.y *= v0.y;
                v1.x = fmaxf(cc[2], 0.f); v1.x *= v1.x;
                v1.y = fmaxf(cc[3], 0.f); v1.y *= v1.y;
                *reinterpret_cast<float2*>(g_act + r0g + gc) = v0;
                *reinterpret_cast<float2*>(g_act + r1g + gc) = v1;
            }
        }
    } else {
#pragma unroll
        for (int mi = 0; mi < 2; mi++) {
            int rl0 = row0 + wm * 32 + mi * 16 + g4;
            int tok0 = -1, tok1 = -1;
            float sc0 = 0.f, sc1 = 0.f;
            if (rl0 < cnt)     { tok0 = g_sorted[obase + rl0];     sc0 = g_scale[tok0]; }
            if (rl0 + 8 < cnt) { tok1 = g_sorted[obase + rl0 + 8]; sc1 = g_scale[tok1]; }
#pragma unroll
            for (int nt = 0; nt < 4; nt++) {
                int gc = coln0 + wn * 32 + nt * 8 + t4 * 2;
                float* cc = acc[mi][nt];
                if (tok0 >= 0) {
                    size_t o = (size_t)tok0 * C_DIM + gc;
                    float2 xv = *reinterpret_cast<const float2*>(x + o);
                    float2 ov; ov.x = xv.x + cc[0] * sc0; ov.y = xv.y + cc[1] * sc0;
                    *reinterpret_cast<float2*>(out + o) = ov;
                }
                if (tok1 >= 0) {
                    size_t o = (size_t)tok1 * C_DIM + gc;
                    float2 xv = *reinterpret_cast<const float2*>(x + o);
                    float2 ov; ov.x = xv.x + cc[2] * sc1; ov.y = xv.y + cc[3] * sc1;
                    *reinterpret_cast<float2*>(out + o) = ov;
                }
            }
        }
    }
}

// ---------------------------------------------------------------------------
extern "C" void kernel_launch(void* const* d_in, const int* in_sizes, int n_in,
                              void* d_out, int out_size)
{
    const float* x       = (const float*)d_in[0];
    const int*   winners = (const int*)  d_in[1];
    const float* gamma   = (const float*)d_in[2];
    const float* beta    = (const float*)d_in[3];
    const float* w1      = (const float*)d_in[4];
    const float* w2      = (const float*)d_in[5];
    const float* wc      = (const float*)d_in[6];
    const float* bc      = (const float*)d_in[7];
    float* out = (float*)d_out;

    const int SMEM = 2 * STAGE;   // 74752 B dynamic
    cudaFuncSetAttribute(gemm_mma<true>,  cudaFuncAttributeMaxDynamicSharedMemorySize, SMEM);
    cudaFuncSetAttribute(gemm_mma<false>, cudaFuncAttributeMaxDynamicSharedMemorySize, SMEM);

    init_kernel<<<1, 32>>>();
    ln_conf_kernel<<<N_TOK, 256>>>(x, winners, gamma, beta, wc, bc);
    scan_kernel<<<1, 32>>>();
    scatter_kernel<<<N_TOK / 256, 256>>>(winners);

    gemm_mma<true><<<dim3(H_DIM / 128, PADDED_CAP / 128, E_NUM), 512, SMEM>>>(w1, x, out);
    gemm_mma<false><<<dim3(C_DIM / 128, PADDED_CAP / 128, E_NUM), 512, SMEM>>>(w2, x, out);
}

// round 11
// speedup vs baseline: 21.8078x; 2.7537x over previous
#include <cuda_runtime.h>
#include <cuda_fp16.h>
#include <stdint.h>
#include <math.h>

#define N_TOK 8192
#define C_DIM 1024
#define H_DIM 4096
#define E_NUM 5
#define PADDED_CAP (N_TOK + E_NUM * 128)   // 8832

// ---------------------------------------------------------------------------
// Device scratch (allocation-free per harness rules)
// NOTE: activations in device globals are fine (R5-R10); staging WEIGHTS in
// device globals is a proven 8-11x regression (R6/R8) — weights are always
// read straight from the harness input pointers.
// ---------------------------------------------------------------------------
__device__ float g_scale[N_TOK];
__device__ int   g_sorted[N_TOK];
__device__ int   g_count[E_NUM];
__device__ int   g_offset[E_NUM + 1];
__device__ int   g_poff[E_NUM + 1];
__device__ int   g_cursor[E_NUM];

__device__ __align__(16) __half g_h_f16[(size_t)N_TOK * C_DIM];        // layernormed tokens
__device__ __align__(16) __half g_act_f16[(size_t)PADDED_CAP * H_DIM]; // relu^2 activations

// ---------------------------------------------------------------------------
// PTX helpers
// ---------------------------------------------------------------------------
__device__ __forceinline__ uint32_t smem_u32(const void* p) {
    uint32_t a;
    asm("{ .reg .u64 t; cvta.to.shared.u64 t, %1; cvt.u32.u64 %0, t; }" : "=r"(a) : "l"(p));
    return a;
}
__device__ __forceinline__ uint32_t lds32(uint32_t a) {
    uint32_t v;
    asm volatile("ld.shared.b32 %0, [%1];" : "=r"(v) : "r"(a));
    return v;
}
__device__ __forceinline__ void mma16816(float* c, const uint32_t* a, uint32_t b0, uint32_t b1) {
    asm volatile("mma.sync.aligned.m16n8k16.row.col.f32.f16.f16.f32 "
                 "{%0,%1,%2,%3}, {%4,%5,%6,%7}, {%8,%9}, {%0,%1,%2,%3};"
                 : "+f"(c[0]), "+f"(c[1]), "+f"(c[2]), "+f"(c[3])
                 : "r"(a[0]), "r"(a[1]), "r"(a[2]), "r"(a[3]), "r"(b0), "r"(b1));
}
__device__ __forceinline__ uint32_t pack_f16(float x, float y) {
    __half2 h = __floats2half2_rn(x, y);
    return *reinterpret_cast<uint32_t*>(&h);
}

// ---------------------------------------------------------------------------
// Small pipeline kernels (validated)
// ---------------------------------------------------------------------------
__global__ void init_kernel() {
    if (threadIdx.x < E_NUM) { g_count[threadIdx.x] = 0; g_cursor[threadIdx.x] = 0; }
}

__global__ void __launch_bounds__(256) ln_conf_kernel(
    const float* __restrict__ x, const int* __restrict__ winners,
    const float* __restrict__ gamma, const float* __restrict__ beta,
    const float* __restrict__ wc, const float* __restrict__ bc)
{
    int n = blockIdx.x, tid = threadIdx.x;
    const float* xr = x + (size_t)n * C_DIM;
    float xv[4], s = 0.f, s2 = 0.f;
#pragma unroll
    for (int i = 0; i < 4; i++) { float v = xr[tid + 256 * i]; xv[i] = v; s += v; s2 += v * v; }
#pragma unroll
    for (int off = 16; off > 0; off >>= 1) {
        s  += __shfl_down_sync(0xffffffffu, s,  off);
        s2 += __shfl_down_sync(0xffffffffu, s2, off);
    }
    __shared__ float sh1[8], sh2[8];
    __shared__ float s_mean, s_rstd;
    int warp = tid >> 5, lane = tid & 31;
    if (lane == 0) { sh1[warp] = s; sh2[warp] = s2; }
    __syncthreads();
    if (tid == 0) {
        float ts = 0.f, ts2 = 0.f;
#pragma unroll
        for (int w = 0; w < 8; w++) { ts += sh1[w]; ts2 += sh2[w]; }
        float mean = ts * (1.f / C_DIM);
        float var = ts2 * (1.f / C_DIM) - mean * mean;
        s_mean = mean; s_rstd = rsqrtf(var + 1e-5f);
    }
    __syncthreads();
    float mean = s_mean, rstd = s_rstd;
    int win = winners[n];
    const float* wcr = wc + (size_t)win * C_DIM;
    float dot = 0.f;
#pragma unroll
    for (int i = 0; i < 4; i++) {
        int c = tid + 256 * i;
        float hv = (xv[i] - mean) * rstd * gamma[c] + beta[c];
        g_h_f16[(size_t)n * C_DIM + c] = __float2half_rn(hv);
        dot += hv * wcr[c];
    }
#pragma unroll
    for (int off = 16; off > 0; off >>= 1) dot += __shfl_down_sync(0xffffffffu, dot, off);
    if (lane == 0) sh1[warp] = dot;
    __syncthreads();
    if (tid == 0) {
        float t = 0.f;
#pragma unroll
        for (int w = 0; w < 8; w++) t += sh1[w];
        t += bc[win];
        float conf = 1.f / (1.f + expf(-t));
        g_scale[n] = conf / (conf + 1e-6f);
        atomicAdd(&g_count[win], 1);
    }
}

__global__ void scan_kernel() {
    if (threadIdx.x == 0) {
        int acc = 0, pacc = 0;
        g_offset[0] = 0; g_poff[0] = 0;
        for (int e = 0; e < E_NUM; e++) {
            int c = g_count[e];
            acc += c;
            g_offset[e + 1] = acc;
            g_cursor[e] = g_offset[e];
            pacc += ((c + 127) / 128) * 128;
            g_poff[e + 1] = pacc;
        }
    }
}

__global__ void scatter_kernel(const int* __restrict__ winners) {
    int n = blockIdx.x * blockDim.x + threadIdx.x;
    if (n < N_TOK) {
        int e = winners[n];
        int pos = atomicAdd(&g_cursor[e], 1);
        g_sorted[pos] = n;
    }
}

// ---------------------------------------------------------------------------
// HMMA GEMM, pure fp16 (1 MMA product per tile; 3x fewer MACs than bf16 split).
// CTA 128x128, BK=32, 8 warps (2M x 4N), warp tile 64x32, 2 CTAs/SM.
// A smem: [m 128][k 32] fp16, 64B rows, XOR group swizzle
//   phys(m, kp) = m*64 + (((kp>>2) ^ ((m>>1)&3))<<4) + ((kp&3)<<2)   (kp = k-pair)
// B smem: [k2 16][n 128] fp16x2 slots, row stride 544B (conflict-free).
// A loaded as fp16 LDG.128 (g_h_f16 / g_act_f16); B from raw fp32 weights,
// converted in the staging phase (one pack per 2 values).
// ---------------------------------------------------------------------------
#define BK 32
#define ST_B   8192
#define B_ROWB 544
#define STAGE  16896          // 8192 + 16*544

template<bool G1>
__global__ void __launch_bounds__(256, 2) gemm_mma(
    const float* __restrict__ w,      // G1: w1 [E][C][H]; G2: w2 [E][H][C]
    const float* __restrict__ x,
    float* __restrict__ out)
{
    constexpr int K  = G1 ? C_DIM : H_DIM;   // reduction dim
    constexpr int NB = G1 ? H_DIM : C_DIM;   // output-feature dim
    constexpr int NC = K / BK;

    int e     = blockIdx.z;
    int pbase = g_poff[e];
    int pcnt  = g_poff[e + 1] - pbase;
    int row0  = blockIdx.y * 128;
    if (row0 >= pcnt) return;
    int coln0 = blockIdx.x * 128;
    int prow0 = pbase + row0;

    __shared__ __align__(16) char sm[2 * STAGE];
    uint32_t sb = smem_u32(sm);

    int tid = threadIdx.x, lane = tid & 31, wid = tid >> 5;
    int wm = wid & 1, wn = wid >> 1;
    int g4 = lane >> 2, t4 = lane & 3;

    int obase = g_offset[e];
    int cnt   = g_offset[e + 1] - obase;

    // ---- A source: 2 rows per thread (fp16), one 16B chunk each ----
    int kq = tid & 3;                         // 16B chunk within 64B row-chunk
    const __half* asrc[2];
    int arow[2];
#pragma unroll
    for (int p = 0; p < 2; p++) {
        int m = p * 64 + (tid >> 2);
        arow[p] = m;
        if (G1) {
            int gr = row0 + m;
            asrc[p] = (gr < cnt) ? (g_h_f16 + (size_t)g_sorted[obase + gr] * C_DIM) : 0;
        } else {
            asrc[p] = g_act_f16 + (size_t)(prow0 + m) * H_DIM;
        }
    }
    // ---- B source: one n column per thread, 8 k-pairs ----
    int nb = tid & 127;
    int khalf = tid >> 7;                     // 0/1 -> k2 base 0 or 8
    const float* bcol = w + (size_t)e * C_DIM * H_DIM + (coln0 + nb);

    float acc[4][4][4];
#pragma unroll
    for (int i = 0; i < 4; i++)
#pragma unroll
        for (int j = 0; j < 4; j++)
#pragma unroll
            for (int q = 0; q < 4; q++) acc[i][j][q] = 0.f;

    // register prefetch buffers
    uint4 ra[2];
    float rb0[8], rb1[8];

    auto sts_chunk = [&](uint32_t soff) {
#pragma unroll
        for (int p = 0; p < 2; p++) {
            int m = arow[p];
            uint32_t off = soff + (uint32_t)(m * 64 + ((kq ^ ((m >> 1) & 3)) << 4));
            *reinterpret_cast<uint4*>(sm + off) = ra[p];
        }
#pragma unroll
        for (int p = 0; p < 8; p++) {
            int k2 = khalf * 8 + p;
            *reinterpret_cast<uint32_t*>(sm + soff + ST_B + k2 * B_ROWB + nb * 4)
                = pack_f16(rb0[p], rb1[p]);
        }
    };
    auto ldg_chunk = [&](int c) {
        int k0 = c * BK;
#pragma unroll
        for (int p = 0; p < 2; p++)
            ra[p] = asrc[p] ? *reinterpret_cast<const uint4*>(asrc[p] + k0 + kq * 8)
                            : make_uint4(0u, 0u, 0u, 0u);
#pragma unroll
        for (int p = 0; p < 8; p++) {
            int k = k0 + 2 * (khalf * 8 + p);
            rb0[p] = bcol[(size_t)k * NB];
            rb1[p] = bcol[(size_t)(k + 1) * NB];
        }
    };

    // prologue
    ldg_chunk(0);
    sts_chunk(0);
    if (NC > 1) ldg_chunk(1);
    __syncthreads();

#pragma unroll 1
    for (int c = 0; c < NC; c++) {
        uint32_t st = sb + (uint32_t)(c & 1) * STAGE;

#pragma unroll
        for (int ks = 0; ks < 2; ks++) {
            uint32_t af[4][4];
#pragma unroll
            for (int mi = 0; mi < 4; mi++) {
                int m = wm * 64 + mi * 16 + g4;
                int s = (m >> 1) & 3;
                uint32_t r0 = st + (uint32_t)(m * 64 + (((ks * 2)     ^ s) << 4) + (t4 << 2));
                uint32_t r2 = st + (uint32_t)(m * 64 + (((ks * 2 + 1) ^ s) << 4) + (t4 << 2));
                af[mi][0] = lds32(r0);
                af[mi][1] = lds32(r0 + 512);   // row m+8, same swizzle key
                af[mi][2] = lds32(r2);
                af[mi][3] = lds32(r2 + 512);
            }
            uint32_t bf[4][2];
#pragma unroll
            for (int nt = 0; nt < 4; nt++) {
                uint32_t bb = st + ST_B
                    + (uint32_t)((ks * 8 + t4) * B_ROWB + (wn * 32 + nt * 8 + g4) * 4);
                bf[nt][0] = lds32(bb);
                bf[nt][1] = lds32(bb + 4 * B_ROWB);
            }
#pragma unroll
            for (int mi = 0; mi < 4; mi++)
#pragma unroll
                for (int nt = 0; nt < 4; nt++)
                    mma16816(acc[mi][nt], af[mi], bf[nt][0], bf[nt][1]);
        }

        if (c + 1 < NC) {
            sts_chunk((uint32_t)((c + 1) & 1) * STAGE);
            if (c + 2 < NC) ldg_chunk(c + 2);
            __syncthreads();
        }
    }

    // ---- epilogue ----
    if (G1) {
#pragma unroll
        for (int mi = 0; mi < 4; mi++) {
            int gr = wm * 64 + mi * 16 + g4;
            size_t r0g = (size_t)(prow0 + gr)     * H_DIM;
            size_t r1g = (size_t)(prow0 + gr + 8) * H_DIM;
#pragma unroll
            for (int nt = 0; nt < 4; nt++) {
                int gc = coln0 + wn * 32 + nt * 8 + t4 * 2;
                float* cc = acc[mi][nt];
                float v0x = fmaxf(cc[0], 0.f); v0x *= v0x;
                float v0y = fmaxf(cc[1], 0.f); v0y *= v0y;
                float v1x = fmaxf(cc[2], 0.f); v1x *= v1x;
                float v1y = fmaxf(cc[3], 0.f); v1y *= v1y;
                *reinterpret_cast<uint32_t*>(g_act_f16 + r0g + gc) = pack_f16(v0x, v0y);
                *reinterpret_cast<uint32_t*>(g_act_f16 + r1g + gc) = pack_f16(v1x, v1y);
            }
        }
    } else {
#pragma unroll
        for (int mi = 0; mi < 4; mi++) {
            int rl0 = row0 + wm * 64 + mi * 16 + g4;
            int tok0 = -1, tok1 = -1;
            float sc0 = 0.f, sc1 = 0.f;
            if (rl0 < cnt)     { tok0 = g_sorted[obase + rl0];     sc0 = g_scale[tok0]; }
            if (rl0 + 8 < cnt) { tok1 = g_sorted[obase + rl0 + 8]; sc1 = g_scale[tok1]; }
#pragma unroll
            for (int nt = 0; nt < 4; nt++) {
                int gc = coln0 + wn * 32 + nt * 8 + t4 * 2;
                float* cc = acc[mi][nt];
                if (tok0 >= 0) {
                    size_t o = (size_t)tok0 * C_DIM + gc;
                    float2 xv = *reinterpret_cast<const float2*>(x + o);
                    float2 ov; ov.x = xv.x + cc[0] * sc0; ov.y = xv.y + cc[1] * sc0;
                    *reinterpret_cast<float2*>(out + o) = ov;
                }
                if (tok1 >= 0) {
                    size_t o = (size_t)tok1 * C_DIM + gc;
                    float2 xv = *reinterpret_cast<const float2*>(x + o);
                    float2 ov; ov.x = xv.x + cc[2] * sc1; ov.y = xv.y + cc[3] * sc1;
                    *reinterpret_cast<float2*>(out + o) = ov;
                }
            }
        }
    }
}

// ---------------------------------------------------------------------------
extern "C" void kernel_launch(void* const* d_in, const int* in_sizes, int n_in,
                              void* d_out, int out_size)
{
    const float* x       = (const float*)d_in[0];
    const int*   winners = (const int*)  d_in[1];
    const float* gamma   = (const float*)d_in[2];
    const float* beta    = (const float*)d_in[3];
    const float* w1      = (const float*)d_in[4];
    const float* w2      = (const float*)d_in[5];
    const float* wc      = (const float*)d_in[6];
    const float* bc      = (const float*)d_in[7];
    float* out = (float*)d_out;

    init_kernel<<<1, 32>>>();
    ln_conf_kernel<<<N_TOK, 256>>>(x, winners, gamma, beta, wc, bc);
    scan_kernel<<<1, 32>>>();
    scatter_kernel<<<N_TOK / 256, 256>>>(winners);

    gemm_mma<true><<<dim3(H_DIM / 128, PADDED_CAP / 128, E_NUM), 256>>>(w1, x, out);
    gemm_mma<false><<<dim3(C_DIM / 128, PADDED_CAP / 128, E_NUM), 256>>>(w2, x, out);
}

// round 12
// speedup vs baseline: 23.5393x; 1.0794x over previous
#include <cuda_runtime.h>
#include <cuda_fp16.h>
#include <stdint.h>
#include <math.h>

#define N_TOK 8192
#define C_DIM 1024
#define H_DIM 4096
#define E_NUM 5
#define PADDED_CAP (N_TOK + E_NUM * 128)   // 8832

// ---------------------------------------------------------------------------
// Device scratch (allocation-free per harness rules)
// NOTE: activations in device globals are fine (R5-R11, incl. cp.async in R8);
// staging WEIGHTS in device globals is a proven 8-11x regression (R6/R8) —
// weights are always read straight from the harness input pointers.
// ---------------------------------------------------------------------------
__device__ float g_scale[N_TOK];
__device__ int   g_sorted[N_TOK];
__device__ int   g_count[E_NUM];
__device__ int   g_offset[E_NUM + 1];
__device__ int   g_poff[E_NUM + 1];
__device__ int   g_cursor[E_NUM];

__device__ __align__(16) __half g_h_f16[(size_t)N_TOK * C_DIM];        // layernormed tokens
__device__ __align__(16) __half g_act_f16[(size_t)PADDED_CAP * H_DIM]; // relu^2 activations

// ---------------------------------------------------------------------------
// PTX helpers
// ---------------------------------------------------------------------------
__device__ __forceinline__ uint32_t smem_u32(const void* p) {
    uint32_t a;
    asm("{ .reg .u64 t; cvta.to.shared.u64 t, %1; cvt.u32.u64 %0, t; }" : "=r"(a) : "l"(p));
    return a;
}
__device__ __forceinline__ uint32_t lds32(uint32_t a) {
    uint32_t v;
    asm volatile("ld.shared.b32 %0, [%1];" : "=r"(v) : "r"(a));
    return v;
}
__device__ __forceinline__ void cp16s(uint32_t dst, const void* src, uint32_t sz) {
    asm volatile("cp.async.cg.shared.global [%0], [%1], 16, %2;" :: "r"(dst), "l"(src), "r"(sz));
}
__device__ __forceinline__ void cp_commit() {
    asm volatile("cp.async.commit_group;" ::: "memory");
}
__device__ __forceinline__ void cp_wait0() {
    asm volatile("cp.async.wait_group 0;" ::: "memory");
}
__device__ __forceinline__ void mma16816(float* c, const uint32_t* a, uint32_t b0, uint32_t b1) {
    asm volatile("mma.sync.aligned.m16n8k16.row.col.f32.f16.f16.f32 "
                 "{%0,%1,%2,%3}, {%4,%5,%6,%7}, {%8,%9}, {%0,%1,%2,%3};"
                 : "+f"(c[0]), "+f"(c[1]), "+f"(c[2]), "+f"(c[3])
                 : "r"(a[0]), "r"(a[1]), "r"(a[2]), "r"(a[3]), "r"(b0), "r"(b1));
}
__device__ __forceinline__ uint32_t pack_f16(float x, float y) {
    __half2 h = __floats2half2_rn(x, y);
    return *reinterpret_cast<uint32_t*>(&h);
}

// ---------------------------------------------------------------------------
// Small pipeline kernels (validated)
// ---------------------------------------------------------------------------
__global__ void init_kernel() {
    if (threadIdx.x < E_NUM) { g_count[threadIdx.x] = 0; g_cursor[threadIdx.x] = 0; }
}

__global__ void __launch_bounds__(256) ln_conf_kernel(
    const float* __restrict__ x, const int* __restrict__ winners,
    const float* __restrict__ gamma, const float* __restrict__ beta,
    const float* __restrict__ wc, const float* __restrict__ bc)
{
    int n = blockIdx.x, tid = threadIdx.x;
    const float* xr = x + (size_t)n * C_DIM;
    float xv[4], s = 0.f, s2 = 0.f;
#pragma unroll
    for (int i = 0; i < 4; i++) { float v = xr[tid + 256 * i]; xv[i] = v; s += v; s2 += v * v; }
#pragma unroll
    for (int off = 16; off > 0; off >>= 1) {
        s  += __shfl_down_sync(0xffffffffu, s,  off);
        s2 += __shfl_down_sync(0xffffffffu, s2, off);
    }
    __shared__ float sh1[8], sh2[8];
    __shared__ float s_mean, s_rstd;
    int warp = tid >> 5, lane = tid & 31;
    if (lane == 0) { sh1[warp] = s; sh2[warp] = s2; }
    __syncthreads();
    if (tid == 0) {
        float ts = 0.f, ts2 = 0.f;
#pragma unroll
        for (int w = 0; w < 8; w++) { ts += sh1[w]; ts2 += sh2[w]; }
        float mean = ts * (1.f / C_DIM);
        float var = ts2 * (1.f / C_DIM) - mean * mean;
        s_mean = mean; s_rstd = rsqrtf(var + 1e-5f);
    }
    __syncthreads();
    float mean = s_mean, rstd = s_rstd;
    int win = winners[n];
    const float* wcr = wc + (size_t)win * C_DIM;
    float dot = 0.f;
#pragma unroll
    for (int i = 0; i < 4; i++) {
        int c = tid + 256 * i;
        float hv = (xv[i] - mean) * rstd * gamma[c] + beta[c];
        g_h_f16[(size_t)n * C_DIM + c] = __float2half_rn(hv);
        dot += hv * wcr[c];
    }
#pragma unroll
    for (int off = 16; off > 0; off >>= 1) dot += __shfl_down_sync(0xffffffffu, dot, off);
    if (lane == 0) sh1[warp] = dot;
    __syncthreads();
    if (tid == 0) {
        float t = 0.f;
#pragma unroll
        for (int w = 0; w < 8; w++) t += sh1[w];
        t += bc[win];
        float conf = 1.f / (1.f + expf(-t));
        g_scale[n] = conf / (conf + 1e-6f);
        atomicAdd(&g_count[win], 1);
    }
}

__global__ void scan_kernel() {
    if (threadIdx.x == 0) {
        int acc = 0, pacc = 0;
        g_offset[0] = 0; g_poff[0] = 0;
        for (int e = 0; e < E_NUM; e++) {
            int c = g_count[e];
            acc += c;
            g_offset[e + 1] = acc;
            g_cursor[e] = g_offset[e];
            pacc += ((c + 127) / 128) * 128;
            g_poff[e + 1] = pacc;
        }
    }
}

__global__ void scatter_kernel(const int* __restrict__ winners) {
    int n = blockIdx.x * blockDim.x + threadIdx.x;
    if (n < N_TOK) {
        int e = winners[n];
        int pos = atomicAdd(&g_cursor[e], 1);
        g_sorted[pos] = n;
    }
}

// ---------------------------------------------------------------------------
// HMMA GEMM, pure fp16 (1 MMA product per tile), CTA 128x128, BK=32,
// 8 warps (2M x 4N), warp tile 64x32, 2 CTAs/SM, double-buffered.
// A: cp.async fp16 direct from g_h_f16 (gathered) / g_act_f16 into swizzled
//    smem (R8-proven path); zero-fill for padding rows via src-size 0.
// B: fp32 weights from harness pointer (R6/R8 law), coalesced column LDG,
//    register-staged, packed to fp16 in the inter-compute gap.
// A smem: [m 128][k 32] fp16, 64B rows, XOR group swizzle
//   phys(m, kp) = m*64 + (((kp>>2) ^ ((m>>1)&3))<<4) + ((kp&3)<<2)
// B smem: [k2 16][n 128] fp16x2 slots, row stride 544B.
// ---------------------------------------------------------------------------
#define BK 32
#define ST_B   8192
#define B_ROWB 544
#define STAGE  16896          // 8192 + 16*544

template<bool G1>
__global__ void __launch_bounds__(256, 2) gemm_mma(
    const float* __restrict__ w,      // G1: w1 [E][C][H]; G2: w2 [E][H][C]
    const float* __restrict__ x,
    float* __restrict__ out)
{
    constexpr int K  = G1 ? C_DIM : H_DIM;   // reduction dim
    constexpr int NB = G1 ? H_DIM : C_DIM;   // output-feature dim
    constexpr int NC = K / BK;

    int e     = blockIdx.z;
    int pbase = g_poff[e];
    int pcnt  = g_poff[e + 1] - pbase;
    int row0  = blockIdx.y * 128;
    if (row0 >= pcnt) return;
    int coln0 = blockIdx.x * 128;
    int prow0 = pbase + row0;

    __shared__ __align__(16) char sm[2 * STAGE];
    uint32_t sb = smem_u32(sm);

    int tid = threadIdx.x, lane = tid & 31, wid = tid >> 5;
    int wm = wid & 1, wn = wid >> 1;
    int g4 = lane >> 2, t4 = lane & 3;

    int obase = g_offset[e];
    int cnt   = g_offset[e + 1] - obase;

    // ---- A cp.async sources: 2 rows per thread, one 16B chunk each ----
    int kq = tid & 3;                         // 16B chunk within 64B row-chunk
    const __half* asrc[2];
    uint32_t asz[2], adst[2];
#pragma unroll
    for (int p = 0; p < 2; p++) {
        int m = p * 64 + (tid >> 2);
        adst[p] = (uint32_t)(m * 64 + ((kq ^ ((m >> 1) & 3)) << 4));
        if (G1) {
            int gr = row0 + m;
            if (gr < cnt) {
                asrc[p] = g_h_f16 + (size_t)g_sorted[obase + gr] * C_DIM + kq * 8;
                asz[p] = 16;
            } else { asrc[p] = g_h_f16; asz[p] = 0; }
        } else {
            asrc[p] = g_act_f16 + (size_t)(prow0 + m) * H_DIM + kq * 8;
            asz[p] = 16;
        }
    }
    // ---- B source: one n column per thread, 8 k-pairs ----
    int nb = tid & 127;
    int khalf = tid >> 7;                     // 0/1 -> k2 base 0 or 8
    const float* bcol = w + (size_t)e * C_DIM * H_DIM + (coln0 + nb);

    float acc[4][4][4];
#pragma unroll
    for (int i = 0; i < 4; i++)
#pragma unroll
        for (int j = 0; j < 4; j++)
#pragma unroll
            for (int q = 0; q < 4; q++) acc[i][j][q] = 0.f;

    float rb0[8], rb1[8];

    auto cpa_chunk = [&](int c, uint32_t soff) {
#pragma unroll
        for (int p = 0; p < 2; p++)
            cp16s(sb + soff + adst[p], asrc[p] + c * BK, asz[p]);
        cp_commit();
    };
    auto stsb_chunk = [&](uint32_t soff) {
#pragma unroll
        for (int p = 0; p < 8; p++) {
            int k2 = khalf * 8 + p;
            *reinterpret_cast<uint32_t*>(sm + soff + ST_B + k2 * B_ROWB + nb * 4)
                = pack_f16(rb0[p], rb1[p]);
        }
    };
    auto ldgb_chunk = [&](int c) {
        int k0 = c * BK;
#pragma unroll
        for (int p = 0; p < 8; p++) {
            int k = k0 + 2 * (khalf * 8 + p);
            rb0[p] = bcol[(size_t)k * NB];
            rb1[p] = bcol[(size_t)(k + 1) * NB];
        }
    };

    // prologue: chunk0 (A async + B staged); B regs prefetch chunk1
    ldgb_chunk(0);
    cpa_chunk(0, 0);
    stsb_chunk(0);
    if (NC > 1) ldgb_chunk(1);
    cp_wait0();
    __syncthreads();

#pragma unroll 1
    for (int c = 0; c < NC; c++) {
        uint32_t st = sb + (uint32_t)(c & 1) * STAGE;

        // issue A copy for c+1 into the freed buffer (lands during compute)
        if (c + 1 < NC) cpa_chunk(c + 1, (uint32_t)((c + 1) & 1) * STAGE);

        // ---- compute chunk c ----
#pragma unroll
        for (int ks = 0; ks < 2; ks++) {
            uint32_t af[4][4];
#pragma unroll
            for (int mi = 0; mi < 4; mi++) {
                int m = wm * 64 + mi * 16 + g4;
                int s = (m >> 1) & 3;
                uint32_t r0 = st + (uint32_t)(m * 64 + (((ks * 2)     ^ s) << 4) + (t4 << 2));
                uint32_t r2 = st + (uint32_t)(m * 64 + (((ks * 2 + 1) ^ s) << 4) + (t4 << 2));
                af[mi][0] = lds32(r0);
                af[mi][1] = lds32(r0 + 512);   // row m+8, same swizzle key
                af[mi][2] = lds32(r2);
                af[mi][3] = lds32(r2 + 512);
            }
            uint32_t bf[4][2];
#pragma unroll
            for (int nt = 0; nt < 4; nt++) {
                uint32_t bb = st + ST_B
                    + (uint32_t)((ks * 8 + t4) * B_ROWB + (wn * 32 + nt * 8 + g4) * 4);
                bf[nt][0] = lds32(bb);
                bf[nt][1] = lds32(bb + 4 * B_ROWB);
            }
#pragma unroll
            for (int mi = 0; mi < 4; mi++)
#pragma unroll
                for (int nt = 0; nt < 4; nt++)
                    mma16816(acc[mi][nt], af[mi], bf[nt][0], bf[nt][1]);
        }

        // ---- stage B(c+1), prefetch B(c+2), wait for A(c+1), barrier ----
        if (c + 1 < NC) {
            stsb_chunk((uint32_t)((c + 1) & 1) * STAGE);
            if (c + 2 < NC) ldgb_chunk(c + 2);
            cp_wait0();
            __syncthreads();
        }
    }

    // ---- epilogue ----
    if (G1) {
#pragma unroll
        for (int mi = 0; mi < 4; mi++) {
            int gr = wm * 64 + mi * 16 + g4;
            size_t r0g = (size_t)(prow0 + gr)     * H_DIM;
            size_t r1g = (size_t)(prow0 + gr + 8) * H_DIM;
#pragma unroll
            for (int nt = 0; nt < 4; nt++) {
                int gc = coln0 + wn * 32 + nt * 8 + t4 * 2;
                float* cc = acc[mi][nt];
                float v0x = fmaxf(cc[0], 0.f); v0x *= v0x;
                float v0y = fmaxf(cc[1], 0.f); v0y *= v0y;
                float v1x = fmaxf(cc[2], 0.f); v1x *= v1x;
                float v1y = fmaxf(cc[3], 0.f); v1y *= v1y;
                *reinterpret_cast<uint32_t*>(g_act_f16 + r0g + gc) = pack_f16(v0x, v0y);
                *reinterpret_cast<uint32_t*>(g_act_f16 + r1g + gc) = pack_f16(v1x, v1y);
            }
        }
    } else {
#pragma unroll
        for (int mi = 0; mi < 4; mi++) {
            int rl0 = row0 + wm * 64 + mi * 16 + g4;
            int tok0 = -1, tok1 = -1;
            float sc0 = 0.f, sc1 = 0.f;
            if (rl0 < cnt)     { tok0 = g_sorted[obase + rl0];     sc0 = g_scale[tok0]; }
            if (rl0 + 8 < cnt) { tok1 = g_sorted[obase + rl0 + 8]; sc1 = g_scale[tok1]; }
#pragma unroll
            for (int nt = 0; nt < 4; nt++) {
                int gc = coln0 + wn * 32 + nt * 8 + t4 * 2;
                float* cc = acc[mi][nt];
                if (tok0 >= 0) {
                    size_t o = (size_t)tok0 * C_DIM + gc;
                    float2 xv = *reinterpret_cast<const float2*>(x + o);
                    float2 ov; ov.x = xv.x + cc[0] * sc0; ov.y = xv.y + cc[1] * sc0;
                    *reinterpret_cast<float2*>(out + o) = ov;
                }
                if (tok1 >= 0) {
                    size_t o = (size_t)tok1 * C_DIM + gc;
                    float2 xv = *reinterpret_cast<const float2*>(x + o);
                    float2 ov; ov.x = xv.x + cc[2] * sc1; ov.y = xv.y + cc[3] * sc1;
                    *reinterpret_cast<float2*>(out + o) = ov;
                }
            }
        }
    }
}

// ---------------------------------------------------------------------------
extern "C" void kernel_launch(void* const* d_in, const int* in_sizes, int n_in,
                              void* d_out, int out_size)
{
    const float* x       = (const float*)d_in[0];
    const int*   winners = (const int*)  d_in[1];
    const float* gamma   = (const float*)d_in[2];
    const float* beta    = (const float*)d_in[3];
    const float* w1      = (const float*)d_in[4];
    const float* w2      = (const float*)d_in[5];
    const float* wc      = (const float*)d_in[6];
    const float* bc      = (const float*)d_in[7];
    float* out = (float*)d_out;

    init_kernel<<<1, 32>>>();
    ln_conf_kernel<<<N_TOK, 256>>>(x, winners, gamma, beta, wc, bc);
    scan_kernel<<<1, 32>>>();
    scatter_kernel<<<N_TOK / 256, 256>>>(winners);

    gemm_mma<true><<<dim3(H_DIM / 128, PADDED_CAP / 128, E_NUM), 256>>>(w1, x, out);
    gemm_mma<false><<<dim3(C_DIM / 128, PADDED_CAP / 128, E_NUM), 256>>>(w2, x, out);
}